// round 2
// baseline (speedup 1.0000x reference)
#include <cuda_runtime.h>

#define M_TOK 32768
#define H_DIM 2048
#define DMID  1024
#define DOUT  256

#define BM 128
#define BN 64
#define BK 32
#define NT 256

// 134 MB scratch for intermediate h = mish(X@W1^T + b1)
__device__ float g_h[(size_t)M_TOK * DMID];

__device__ __forceinline__ unsigned f2tf32(float x) {
    unsigned u;
    asm("cvt.rna.tf32.f32 %0, %1;" : "=r"(u) : "f"(x));
    return u;
}

__device__ __forceinline__ void mma8(float c[4], const unsigned a[4], const unsigned b[2]) {
    asm volatile(
        "mma.sync.aligned.m16n8k8.row.col.f32.tf32.tf32.f32 "
        "{%0,%1,%2,%3}, {%4,%5,%6,%7}, {%8,%9}, {%0,%1,%2,%3};\n"
        : "+f"(c[0]), "+f"(c[1]), "+f"(c[2]), "+f"(c[3])
        : "r"(a[0]), "r"(a[1]), "r"(a[2]), "r"(a[3]), "r"(b[0]), "r"(b[1]));
}

// mish(x) = x * tanh(softplus(x)) = x * (t^2 + 2t) / (t^2 + 2t + 2), t = e^x
__device__ __forceinline__ float mish_f(float x) {
    if (x > 20.0f) return x;
    float t = __expf(x);
    float n = t * t + 2.0f * t;
    return x * (n / (n + 2.0f));
}

// ---------------------------------------------------------------------------
// Kernel 1: h = mish( gather(X)[m] @ W1^T + b1 ),  M=32768, N=1024, K=2048
// ---------------------------------------------------------------------------
__global__ __launch_bounds__(NT) void gemm1_mish_kernel(
    const float* __restrict__ hidden, const float* __restrict__ W1,
    const float* __restrict__ b1, const int* __restrict__ flat_idx)
{
    __shared__ unsigned As[BK][BM + 4];   // k-major: conflict-free frag loads
    __shared__ unsigned Bs[BK][BN + 4];
    __shared__ int rowIdx[BM];

    const int tid = threadIdx.x;
    const int m0 = blockIdx.y * BM;
    const int n0 = blockIdx.x * BN;

    if (tid < BM) rowIdx[tid] = flat_idx[m0 + tid];
    __syncthreads();

    const int lane = tid & 31;
    const int warp = tid >> 5;
    const int warpM = warp >> 1;   // 0..3  (32 rows each)
    const int warpN = warp & 1;    // 0..1  (32 cols each)
    const int g  = lane >> 2;      // groupID
    const int tg = lane & 3;       // thread-in-group

    float acc[2][4][4];
    #pragma unroll
    for (int mi = 0; mi < 2; mi++)
        #pragma unroll
        for (int ni = 0; ni < 4; ni++)
            #pragma unroll
            for (int j = 0; j < 4; j++) acc[mi][ni][j] = 0.f;

    for (int k0 = 0; k0 < H_DIM; k0 += BK) {
        // A tile: 128 rows x 32 k, gathered rows, float4 along k
        for (int i = tid; i < BM * 8; i += NT) {
            int r = i >> 3, kq = i & 7;
            const float4 v = *reinterpret_cast<const float4*>(
                hidden + (size_t)rowIdx[r] * H_DIM + k0 + kq * 4);
            As[kq*4+0][r] = f2tf32(v.x);
            As[kq*4+1][r] = f2tf32(v.y);
            As[kq*4+2][r] = f2tf32(v.z);
            As[kq*4+3][r] = f2tf32(v.w);
        }
        // B tile: 64 rows (n) x 32 k
        for (int i = tid; i < BN * 8; i += NT) {
            int r = i >> 3, kq = i & 7;
            const float4 v = *reinterpret_cast<const float4*>(
                W1 + (size_t)(n0 + r) * H_DIM + k0 + kq * 4);
            Bs[kq*4+0][r] = f2tf32(v.x);
            Bs[kq*4+1][r] = f2tf32(v.y);
            Bs[kq*4+2][r] = f2tf32(v.z);
            Bs[kq*4+3][r] = f2tf32(v.w);
        }
        __syncthreads();

        #pragma unroll
        for (int ks = 0; ks < BK; ks += 8) {
            unsigned a[2][4], b[4][2];
            #pragma unroll
            for (int mi = 0; mi < 2; mi++) {
                int r0 = warpM * 32 + mi * 16 + g;
                a[mi][0] = As[ks + tg][r0];
                a[mi][1] = As[ks + tg][r0 + 8];
                a[mi][2] = As[ks + tg + 4][r0];
                a[mi][3] = As[ks + tg + 4][r0 + 8];
            }
            #pragma unroll
            for (int ni = 0; ni < 4; ni++) {
                int c0 = warpN * 32 + ni * 8 + g;
                b[ni][0] = Bs[ks + tg][c0];
                b[ni][1] = Bs[ks + tg + 4][c0];
            }
            #pragma unroll
            for (int mi = 0; mi < 2; mi++)
                #pragma unroll
                for (int ni = 0; ni < 4; ni++)
                    mma8(acc[mi][ni], a[mi], b[ni]);
        }
        __syncthreads();
    }

    // epilogue: bias + mish -> g_h (fp32)
    #pragma unroll
    for (int ni = 0; ni < 4; ni++) {
        int col = n0 + warpN * 32 + ni * 8 + tg * 2;
        float bb0 = b1[col], bb1 = b1[col + 1];
        #pragma unroll
        for (int mi = 0; mi < 2; mi++) {
            int row = m0 + warpM * 32 + mi * 16 + g;
            g_h[(size_t)row * DMID + col]         = mish_f(acc[mi][ni][0] + bb0);
            g_h[(size_t)row * DMID + col + 1]     = mish_f(acc[mi][ni][1] + bb1);
            g_h[(size_t)(row + 8) * DMID + col]   = mish_f(acc[mi][ni][2] + bb0);
            g_h[(size_t)(row + 8) * DMID + col+1] = mish_f(acc[mi][ni][3] + bb1);
        }
    }
}

// ---------------------------------------------------------------------------
// Kernel 2: S = h @ W2^T + b2 ; pooled[seg] += S[row]   M=32768, N=256, K=1024
// ---------------------------------------------------------------------------
__global__ __launch_bounds__(NT) void gemm2_pool_kernel(
    const float* __restrict__ W2, const float* __restrict__ b2,
    const int* __restrict__ segment_ids, float* __restrict__ out)
{
    __shared__ unsigned As[BK][BM + 4];
    __shared__ unsigned Bs[BK][BN + 4];
    __shared__ int segS[BM];

    const int tid = threadIdx.x;
    const int m0 = blockIdx.y * BM;
    const int n0 = blockIdx.x * BN;

    if (tid < BM) segS[tid] = segment_ids[m0 + tid];
    __syncthreads();

    const int lane = tid & 31;
    const int warp = tid >> 5;
    const int warpM = warp >> 1;
    const int warpN = warp & 1;
    const int g  = lane >> 2;
    const int tg = lane & 3;

    float acc[2][4][4];
    #pragma unroll
    for (int mi = 0; mi < 2; mi++)
        #pragma unroll
        for (int ni = 0; ni < 4; ni++)
            #pragma unroll
            for (int j = 0; j < 4; j++) acc[mi][ni][j] = 0.f;

    for (int k0 = 0; k0 < DMID; k0 += BK) {
        for (int i = tid; i < BM * 8; i += NT) {
            int r = i >> 3, kq = i & 7;
            const float4 v = *reinterpret_cast<const float4*>(
                g_h + (size_t)(m0 + r) * DMID + k0 + kq * 4);
            As[kq*4+0][r] = f2tf32(v.x);
            As[kq*4+1][r] = f2tf32(v.y);
            As[kq*4+2][r] = f2tf32(v.z);
            As[kq*4+3][r] = f2tf32(v.w);
        }
        for (int i = tid; i < BN * 8; i += NT) {
            int r = i >> 3, kq = i & 7;
            const float4 v = *reinterpret_cast<const float4*>(
                W2 + (size_t)(n0 + r) * DMID + k0 + kq * 4);
            Bs[kq*4+0][r] = f2tf32(v.x);
            Bs[kq*4+1][r] = f2tf32(v.y);
            Bs[kq*4+2][r] = f2tf32(v.z);
            Bs[kq*4+3][r] = f2tf32(v.w);
        }
        __syncthreads();

        #pragma unroll
        for (int ks = 0; ks < BK; ks += 8) {
            unsigned a[2][4], b[4][2];
            #pragma unroll
            for (int mi = 0; mi < 2; mi++) {
                int r0 = warpM * 32 + mi * 16 + g;
                a[mi][0] = As[ks + tg][r0];
                a[mi][1] = As[ks + tg][r0 + 8];
                a[mi][2] = As[ks + tg + 4][r0];
                a[mi][3] = As[ks + tg + 4][r0 + 8];
            }
            #pragma unroll
            for (int ni = 0; ni < 4; ni++) {
                int c0 = warpN * 32 + ni * 8 + g;
                b[ni][0] = Bs[ks + tg][c0];
                b[ni][1] = Bs[ks + tg + 4][c0];
            }
            #pragma unroll
            for (int mi = 0; mi < 2; mi++)
                #pragma unroll
                for (int ni = 0; ni < 4; ni++)
                    mma8(acc[mi][ni], a[mi], b[ni]);
        }
        __syncthreads();
    }

    // epilogue: bias + segment-sum via atomics
    #pragma unroll
    for (int ni = 0; ni < 4; ni++) {
        int col = n0 + warpN * 32 + ni * 8 + tg * 2;
        float bb0 = b2[col], bb1 = b2[col + 1];
        #pragma unroll
        for (int mi = 0; mi < 2; mi++) {
            int r = warpM * 32 + mi * 16 + g;
            int s0 = segS[r];
            int s1 = segS[r + 8];
            atomicAdd(&out[s0 * DOUT + col],     acc[mi][ni][0] + bb0);
            atomicAdd(&out[s0 * DOUT + col + 1], acc[mi][ni][1] + bb1);
            atomicAdd(&out[s1 * DOUT + col],     acc[mi][ni][2] + bb0);
            atomicAdd(&out[s1 * DOUT + col + 1], acc[mi][ni][3] + bb1);
        }
    }
}

__global__ void zero_kernel(float* p, int n) {
    int i = blockIdx.x * blockDim.x + threadIdx.x;
    if (i < n) p[i] = 0.0f;
}

extern "C" void kernel_launch(void* const* d_in, const int* in_sizes, int n_in,
                              void* d_out, int out_size) {
    const float* hidden   = (const float*)d_in[0];
    const float* W1       = (const float*)d_in[1];
    const float* b1       = (const float*)d_in[2];
    const float* W2       = (const float*)d_in[3];
    const float* b2       = (const float*)d_in[4];
    const int*   flat_idx = (const int*)d_in[5];
    const int*   seg_ids  = (const int*)d_in[6];
    float* out = (float*)d_out;

    zero_kernel<<<(out_size + 255) / 256, 256>>>(out, out_size);

    dim3 g1(DMID / BN, M_TOK / BM);   // (16, 256)
    gemm1_mish_kernel<<<g1, NT>>>(hidden, W1, b1, flat_idx);

    dim3 g2(DOUT / BN, M_TOK / BM);   // (4, 256)
    gemm2_pool_kernel<<<g2, NT>>>(W2, b2, seg_ids, out);
}

// round 3
// speedup vs baseline: 1.0076x; 1.0076x over previous
#include <cuda_runtime.h>

#define M_TOK 32768
#define H_DIM 2048
#define DMID  1024
#define DOUT  256

#define BM 128
#define BN 64
#define BK 32
#define NT 256

// 134 MB scratch for intermediate h = mish(X@W1^T + b1)
__device__ float g_h[(size_t)M_TOK * DMID];

__device__ __forceinline__ unsigned f2tf32(float x) {
    unsigned u;
    asm("cvt.rna.tf32.f32 %0, %1;" : "=r"(u) : "f"(x));
    return u;
}

__device__ __forceinline__ void mma8(float c[4], const unsigned a[4], const unsigned b[2]) {
    asm volatile(
        "mma.sync.aligned.m16n8k8.row.col.f32.tf32.tf32.f32 "
        "{%0,%1,%2,%3}, {%4,%5,%6,%7}, {%8,%9}, {%0,%1,%2,%3};\n"
        : "+f"(c[0]), "+f"(c[1]), "+f"(c[2]), "+f"(c[3])
        : "r"(a[0]), "r"(a[1]), "r"(a[2]), "r"(a[3]), "r"(b[0]), "r"(b[1]));
}

// mish(x) = x * tanh(softplus(x)) = x * (t^2 + 2t) / (t^2 + 2t + 2), t = e^x
__device__ __forceinline__ float mish_f(float x) {
    if (x > 20.0f) return x;
    float t = __expf(x);
    float n = t * t + 2.0f * t;
    return x * (n / (n + 2.0f));
}

// ---------------------------------------------------------------------------
// Kernel 1: h = mish( gather(X)[m] @ W1^T + b1 ),  M=32768, N=1024, K=2048
// ---------------------------------------------------------------------------
__global__ __launch_bounds__(NT) void gemm1_mish_kernel(
    const float* __restrict__ hidden, const float* __restrict__ W1,
    const float* __restrict__ b1, const int* __restrict__ flat_idx)
{
    __shared__ unsigned As[BK][BM + 4];   // k-major: conflict-free frag loads
    __shared__ unsigned Bs[BK][BN + 4];
    __shared__ int rowIdx[BM];

    const int tid = threadIdx.x;
    const int m0 = blockIdx.y * BM;
    const int n0 = blockIdx.x * BN;

    if (tid < BM) rowIdx[tid] = flat_idx[m0 + tid];
    __syncthreads();

    const int lane = tid & 31;
    const int warp = tid >> 5;
    const int warpM = warp >> 1;   // 0..3  (32 rows each)
    const int warpN = warp & 1;    // 0..1  (32 cols each)
    const int g  = lane >> 2;      // groupID
    const int tg = lane & 3;       // thread-in-group

    float acc[2][4][4];
    #pragma unroll
    for (int mi = 0; mi < 2; mi++)
        #pragma unroll
        for (int ni = 0; ni < 4; ni++)
            #pragma unroll
            for (int j = 0; j < 4; j++) acc[mi][ni][j] = 0.f;

    for (int k0 = 0; k0 < H_DIM; k0 += BK) {
        // A tile: 128 rows x 32 k, gathered rows, float4 along k
        for (int i = tid; i < BM * 8; i += NT) {
            int r = i >> 3, kq = i & 7;
            const float4 v = *reinterpret_cast<const float4*>(
                hidden + (size_t)rowIdx[r] * H_DIM + k0 + kq * 4);
            As[kq*4+0][r] = f2tf32(v.x);
            As[kq*4+1][r] = f2tf32(v.y);
            As[kq*4+2][r] = f2tf32(v.z);
            As[kq*4+3][r] = f2tf32(v.w);
        }
        // B tile: 64 rows (n) x 32 k
        for (int i = tid; i < BN * 8; i += NT) {
            int r = i >> 3, kq = i & 7;
            const float4 v = *reinterpret_cast<const float4*>(
                W1 + (size_t)(n0 + r) * H_DIM + k0 + kq * 4);
            Bs[kq*4+0][r] = f2tf32(v.x);
            Bs[kq*4+1][r] = f2tf32(v.y);
            Bs[kq*4+2][r] = f2tf32(v.z);
            Bs[kq*4+3][r] = f2tf32(v.w);
        }
        __syncthreads();

        #pragma unroll
        for (int ks = 0; ks < BK; ks += 8) {
            unsigned a[2][4], b[4][2];
            #pragma unroll
            for (int mi = 0; mi < 2; mi++) {
                int r0 = warpM * 32 + mi * 16 + g;
                a[mi][0] = As[ks + tg][r0];
                a[mi][1] = As[ks + tg][r0 + 8];
                a[mi][2] = As[ks + tg + 4][r0];
                a[mi][3] = As[ks + tg + 4][r0 + 8];
            }
            #pragma unroll
            for (int ni = 0; ni < 4; ni++) {
                int c0 = warpN * 32 + ni * 8 + g;
                b[ni][0] = Bs[ks + tg][c0];
                b[ni][1] = Bs[ks + tg + 4][c0];
            }
            #pragma unroll
            for (int mi = 0; mi < 2; mi++)
                #pragma unroll
                for (int ni = 0; ni < 4; ni++)
                    mma8(acc[mi][ni], a[mi], b[ni]);
        }
        __syncthreads();
    }

    // epilogue: bias + mish -> g_h (fp32)
    #pragma unroll
    for (int ni = 0; ni < 4; ni++) {
        int col = n0 + warpN * 32 + ni * 8 + tg * 2;
        float bb0 = b1[col], bb1 = b1[col + 1];
        #pragma unroll
        for (int mi = 0; mi < 2; mi++) {
            int row = m0 + warpM * 32 + mi * 16 + g;
            g_h[(size_t)row * DMID + col]         = mish_f(acc[mi][ni][0] + bb0);
            g_h[(size_t)row * DMID + col + 1]     = mish_f(acc[mi][ni][1] + bb1);
            g_h[(size_t)(row + 8) * DMID + col]   = mish_f(acc[mi][ni][2] + bb0);
            g_h[(size_t)(row + 8) * DMID + col+1] = mish_f(acc[mi][ni][3] + bb1);
        }
    }
}

// ---------------------------------------------------------------------------
// Kernel 2: S = h @ W2^T + b2 ; pooled[seg] += S[row]   M=32768, N=256, K=1024
// ---------------------------------------------------------------------------
__global__ __launch_bounds__(NT) void gemm2_pool_kernel(
    const float* __restrict__ W2, const float* __restrict__ b2,
    const int* __restrict__ segment_ids, float* __restrict__ out)
{
    __shared__ unsigned As[BK][BM + 4];
    __shared__ unsigned Bs[BK][BN + 4];
    __shared__ int segS[BM];

    const int tid = threadIdx.x;
    const int m0 = blockIdx.y * BM;
    const int n0 = blockIdx.x * BN;

    if (tid < BM) segS[tid] = segment_ids[m0 + tid];
    __syncthreads();

    const int lane = tid & 31;
    const int warp = tid >> 5;
    const int warpM = warp >> 1;
    const int warpN = warp & 1;
    const int g  = lane >> 2;
    const int tg = lane & 3;

    float acc[2][4][4];
    #pragma unroll
    for (int mi = 0; mi < 2; mi++)
        #pragma unroll
        for (int ni = 0; ni < 4; ni++)
            #pragma unroll
            for (int j = 0; j < 4; j++) acc[mi][ni][j] = 0.f;

    for (int k0 = 0; k0 < DMID; k0 += BK) {
        for (int i = tid; i < BM * 8; i += NT) {
            int r = i >> 3, kq = i & 7;
            const float4 v = *reinterpret_cast<const float4*>(
                g_h + (size_t)(m0 + r) * DMID + k0 + kq * 4);
            As[kq*4+0][r] = f2tf32(v.x);
            As[kq*4+1][r] = f2tf32(v.y);
            As[kq*4+2][r] = f2tf32(v.z);
            As[kq*4+3][r] = f2tf32(v.w);
        }
        for (int i = tid; i < BN * 8; i += NT) {
            int r = i >> 3, kq = i & 7;
            const float4 v = *reinterpret_cast<const float4*>(
                W2 + (size_t)(n0 + r) * DMID + k0 + kq * 4);
            Bs[kq*4+0][r] = f2tf32(v.x);
            Bs[kq*4+1][r] = f2tf32(v.y);
            Bs[kq*4+2][r] = f2tf32(v.z);
            Bs[kq*4+3][r] = f2tf32(v.w);
        }
        __syncthreads();

        #pragma unroll
        for (int ks = 0; ks < BK; ks += 8) {
            unsigned a[2][4], b[4][2];
            #pragma unroll
            for (int mi = 0; mi < 2; mi++) {
                int r0 = warpM * 32 + mi * 16 + g;
                a[mi][0] = As[ks + tg][r0];
                a[mi][1] = As[ks + tg][r0 + 8];
                a[mi][2] = As[ks + tg + 4][r0];
                a[mi][3] = As[ks + tg + 4][r0 + 8];
            }
            #pragma unroll
            for (int ni = 0; ni < 4; ni++) {
                int c0 = warpN * 32 + ni * 8 + g;
                b[ni][0] = Bs[ks + tg][c0];
                b[ni][1] = Bs[ks + tg + 4][c0];
            }
            #pragma unroll
            for (int mi = 0; mi < 2; mi++)
                #pragma unroll
                for (int ni = 0; ni < 4; ni++)
                    mma8(acc[mi][ni], a[mi], b[ni]);
        }
        __syncthreads();
    }

    // epilogue: bias + segment-sum via atomics
    #pragma unroll
    for (int ni = 0; ni < 4; ni++) {
        int col = n0 + warpN * 32 + ni * 8 + tg * 2;
        float bb0 = b2[col], bb1 = b2[col + 1];
        #pragma unroll
        for (int mi = 0; mi < 2; mi++) {
            int r = warpM * 32 + mi * 16 + g;
            int s0 = segS[r];
            int s1 = segS[r + 8];
            atomicAdd(&out[s0 * DOUT + col],     acc[mi][ni][0] + bb0);
            atomicAdd(&out[s0 * DOUT + col + 1], acc[mi][ni][1] + bb1);
            atomicAdd(&out[s1 * DOUT + col],     acc[mi][ni][2] + bb0);
            atomicAdd(&out[s1 * DOUT + col + 1], acc[mi][ni][3] + bb1);
        }
    }
}

__global__ void zero_kernel(float* p, int n) {
    int i = blockIdx.x * blockDim.x + threadIdx.x;
    if (i < n) p[i] = 0.0f;
}

extern "C" void kernel_launch(void* const* d_in, const int* in_sizes, int n_in,
                              void* d_out, int out_size) {
    const float* hidden   = (const float*)d_in[0];
    const float* W1       = (const float*)d_in[1];
    const float* b1       = (const float*)d_in[2];
    const float* W2       = (const float*)d_in[3];
    const float* b2       = (const float*)d_in[4];
    const int*   flat_idx = (const int*)d_in[5];
    const int*   seg_ids  = (const int*)d_in[6];
    float* out = (float*)d_out;

    zero_kernel<<<(out_size + 255) / 256, 256>>>(out, out_size);

    dim3 g1(DMID / BN, M_TOK / BM);   // (16, 256)
    gemm1_mish_kernel<<<g1, NT>>>(hidden, W1, b1, flat_idx);

    dim3 g2(DOUT / BN, M_TOK / BM);   // (4, 256)
    gemm2_pool_kernel<<<g2, NT>>>(W2, b2, seg_ids, out);
}

// round 5
// speedup vs baseline: 2.4655x; 2.4469x over previous
#include <cuda_runtime.h>
#include <cstdint>

#define M_TOK 32768
#define H_DIM 2048
#define DMID  1024
#define DOUT  256

#define BM 128
#define BN 128
#define BK 32
#define NT 256
#define KSTRIDE_W 136                 // words per k-row in smem (conflict-free)
#define STG_BYTES (BK * KSTRIDE_W * 4)   // 17408
#define SMEM_GEMM (4 * STG_BYTES)        // A0 A1 B0 B1 = 69632

__device__ float g_Xp [(size_t)M_TOK * H_DIM];   // [256 panels][2048][128]
__device__ float g_W1p[(size_t)DMID  * H_DIM];   // [8 panels][2048][128]
__device__ float g_W2p[(size_t)DOUT  * DMID];    // [2 panels][1024][128]
__device__ float g_h  [(size_t)M_TOK * DMID];    // [256 panels][1024][128]

__device__ __forceinline__ uint32_t smem_u32(const void* p) {
    uint32_t a;
    asm("{ .reg .u64 t; cvta.to.shared.u64 t, %1; cvt.u32.u64 %0, t; }" : "=r"(a) : "l"(p));
    return a;
}
__device__ __forceinline__ unsigned f2tf32(float x) {
    unsigned u; asm("cvt.rna.tf32.f32 %0, %1;" : "=r"(u) : "f"(x)); return u;
}
__device__ __forceinline__ void cp16(uint32_t dst, const float* src) {
    asm volatile("cp.async.cg.shared.global [%0], [%1], 16;"
                 :: "r"(dst), "l"(__cvta_generic_to_global(src)) : "memory");
}
#define CP_COMMIT() asm volatile("cp.async.commit_group;" ::: "memory")
#define CP_WAIT1()  asm volatile("cp.async.wait_group 1;" ::: "memory")
#define CP_WAIT0()  asm volatile("cp.async.wait_group 0;" ::: "memory")
#define LDSW(v, a)  asm volatile("ld.shared.b32 %0, [%1];" : "=r"(v) : "r"(a))

__device__ __forceinline__ void mma8(float c[4], const unsigned a[4], const unsigned b[2]) {
    asm volatile(
        "mma.sync.aligned.m16n8k8.row.col.f32.tf32.tf32.f32 "
        "{%0,%1,%2,%3}, {%4,%5,%6,%7}, {%8,%9}, {%0,%1,%2,%3};\n"
        : "+f"(c[0]), "+f"(c[1]), "+f"(c[2]), "+f"(c[3])
        : "r"(a[0]), "r"(a[1]), "r"(a[2]), "r"(a[3]), "r"(b[0]), "r"(b[1]));
}
__device__ __forceinline__ float mish_f(float x) {
    float t = __expf(x);
    float n = t * t + 2.0f * t;
    float r = x * __fdividef(n, n + 2.0f);
    return (x > 15.0f) ? x : r;
}

// ---------------------------------------------------------------------------
// Pipelined mainloop: A,B panels are [K][128] pre-rounded tf32-in-fp32.
// ---------------------------------------------------------------------------
__device__ __forceinline__ void gemm_mainloop(
    const float* __restrict__ Ap, const float* __restrict__ Bp, int K,
    uint32_t sbase, float acc[2][8][4])
{
    const int tid = threadIdx.x;
    const int lane = tid & 31, warp = tid >> 5;
    const int warpM = warp >> 1, warpN = warp & 1;
    const int g = lane >> 2, tg = lane & 3;

    uint32_t sA[2] = { sbase,                 sbase + STG_BYTES };
    uint32_t sB[2] = { sbase + 2 * STG_BYTES, sbase + 3 * STG_BYTES };

    // per-thread copy chunks: c = tid + i*256 -> kk = c>>5, mq = c&31
    uint32_t doff[4]; int soff[4];
    #pragma unroll
    for (int i = 0; i < 4; i++) {
        int c = tid + i * 256, kk = c >> 5, mq = c & 31;
        doff[i] = (uint32_t)(kk * (KSTRIDE_W * 4) + mq * 16);
        soff[i] = kk * 128 + mq * 4;
    }

    // prologue: stage 0
    #pragma unroll
    for (int i = 0; i < 4; i++) {
        cp16(sA[0] + doff[i], Ap + soff[i]);
        cp16(sB[0] + doff[i], Bp + soff[i]);
    }
    CP_COMMIT();

    const int S = K / BK;
    for (int s = 0; s < S; s++) {
        const int p = s & 1;
        if (s + 1 < S) {
            const float* a1 = Ap + (size_t)(s + 1) * BK * 128;
            const float* b1 = Bp + (size_t)(s + 1) * BK * 128;
            const int q = p ^ 1;
            #pragma unroll
            for (int i = 0; i < 4; i++) {
                cp16(sA[q] + doff[i], a1 + soff[i]);
                cp16(sB[q] + doff[i], b1 + soff[i]);
            }
            CP_COMMIT();
            CP_WAIT1();
        } else {
            CP_WAIT0();
        }
        __syncthreads();

        const uint32_t aB = sA[p] + (uint32_t)((warpM * 32) * 4);
        const uint32_t bB = sB[p] + (uint32_t)((warpN * 64) * 4);
        #pragma unroll
        for (int ks = 0; ks < BK; ks += 8) {
            unsigned a[2][4], b[8][2];
            const uint32_t rowLo = (uint32_t)((ks + tg) * (KSTRIDE_W * 4));
            const uint32_t rowHi = rowLo + 4 * (KSTRIDE_W * 4);
            #pragma unroll
            for (int mi = 0; mi < 2; mi++) {
                uint32_t o = (uint32_t)((mi * 16 + g) * 4);
                LDSW(a[mi][0], aB + rowLo + o);
                LDSW(a[mi][1], aB + rowLo + o + 32);
                LDSW(a[mi][2], aB + rowHi + o);
                LDSW(a[mi][3], aB + rowHi + o + 32);
            }
            #pragma unroll
            for (int ni = 0; ni < 8; ni++) {
                uint32_t o = (uint32_t)((ni * 8 + g) * 4);
                LDSW(b[ni][0], bB + rowLo + o);
                LDSW(b[ni][1], bB + rowHi + o);
            }
            #pragma unroll
            for (int mi = 0; mi < 2; mi++)
                #pragma unroll
                for (int ni = 0; ni < 8; ni++)
                    mma8(acc[mi][ni], a[mi], b[ni]);
        }
        __syncthreads();
    }
}

// -------- GEMM1: g_h[panel] = mish( Xp @ W1p^T + b1 ), tf32-rounded --------
__global__ __launch_bounds__(NT, 2) void gemm1_kernel(const float* __restrict__ b1)
{
    extern __shared__ char smem[];
    float acc[2][8][4];
    #pragma unroll
    for (int mi = 0; mi < 2; mi++)
        #pragma unroll
        for (int ni = 0; ni < 8; ni++)
            #pragma unroll
            for (int j = 0; j < 4; j++) acc[mi][ni][j] = 0.f;

    const float* Ap = g_Xp  + (size_t)blockIdx.y * (H_DIM * 128);
    const float* Bp = g_W1p + (size_t)blockIdx.x * (H_DIM * 128);
    gemm_mainloop(Ap, Bp, H_DIM, smem_u32(smem), acc);

    const int tid = threadIdx.x, lane = tid & 31, warp = tid >> 5;
    const int warpM = warp >> 1, warpN = warp & 1;
    const int g = lane >> 2, tg = lane & 3;
    const int n0 = blockIdx.x * BN;
    float* hp = g_h + (size_t)blockIdx.y * (DMID * 128);

    #pragma unroll
    for (int ni = 0; ni < 8; ni++) {
        int col = n0 + warpN * 64 + ni * 8 + 2 * tg;
        float bb0 = __ldg(b1 + col), bb1 = __ldg(b1 + col + 1);
        #pragma unroll
        for (int mi = 0; mi < 2; mi++) {
            int rl = warpM * 32 + mi * 16 + g;
            float* p0 = hp + (size_t)col * 128 + rl;
            p0[0]        = __uint_as_float(f2tf32(mish_f(acc[mi][ni][0] + bb0)));
            p0[128]      = __uint_as_float(f2tf32(mish_f(acc[mi][ni][1] + bb1)));
            p0[8]        = __uint_as_float(f2tf32(mish_f(acc[mi][ni][2] + bb0)));
            p0[128 + 8]  = __uint_as_float(f2tf32(mish_f(acc[mi][ni][3] + bb1)));
        }
    }
}

// -------- GEMM2: out[seg] += g_h @ W2p^T + b2 --------
__global__ __launch_bounds__(NT, 2) void gemm2_kernel(
    const float* __restrict__ b2, const int* __restrict__ seg_ids,
    float* __restrict__ out)
{
    extern __shared__ char smem[];
    float acc[2][8][4];
    #pragma unroll
    for (int mi = 0; mi < 2; mi++)
        #pragma unroll
        for (int ni = 0; ni < 8; ni++)
            #pragma unroll
            for (int j = 0; j < 4; j++) acc[mi][ni][j] = 0.f;

    const float* Ap = g_h   + (size_t)blockIdx.y * (DMID * 128);
    const float* Bp = g_W2p + (size_t)blockIdx.x * (DMID * 128);
    gemm_mainloop(Ap, Bp, DMID, smem_u32(smem), acc);

    const int tid = threadIdx.x, lane = tid & 31, warp = tid >> 5;
    const int warpM = warp >> 1, warpN = warp & 1;
    const int g = lane >> 2, tg = lane & 3;
    const int m0 = blockIdx.y * BM;
    const int n0 = blockIdx.x * BN;

    const int segFirst = __ldg(seg_ids + m0);
    const int segLast  = __ldg(seg_ids + m0 + BM - 1);

    if (segFirst == segLast) {
        float* orow = out + (size_t)segFirst * DOUT;
        #pragma unroll
        for (int ni = 0; ni < 8; ni++) {
            float v0 = acc[0][ni][0] + acc[0][ni][2] + acc[1][ni][0] + acc[1][ni][2];
            float v1 = acc[0][ni][1] + acc[0][ni][3] + acc[1][ni][1] + acc[1][ni][3];
            #pragma unroll
            for (int m = 4; m <= 16; m <<= 1) {
                v0 += __shfl_xor_sync(0xffffffffu, v0, m);
                v1 += __shfl_xor_sync(0xffffffffu, v1, m);
            }
            if (lane < 4) {
                int col = n0 + warpN * 64 + ni * 8 + 2 * lane;
                atomicAdd(orow + col,     v0 + 32.0f * __ldg(b2 + col));
                atomicAdd(orow + col + 1, v1 + 32.0f * __ldg(b2 + col + 1));
            }
        }
    } else {
        #pragma unroll
        for (int mi = 0; mi < 2; mi++) {
            int rl = warpM * 32 + mi * 16 + g;
            int sLo = __ldg(seg_ids + m0 + rl);
            int sHi = __ldg(seg_ids + m0 + rl + 8);
            #pragma unroll
            for (int ni = 0; ni < 8; ni++) {
                int col = n0 + warpN * 64 + ni * 8 + 2 * tg;
                float bb0 = __ldg(b2 + col), bb1 = __ldg(b2 + col + 1);
                atomicAdd(out + (size_t)sLo * DOUT + col,     acc[mi][ni][0] + bb0);
                atomicAdd(out + (size_t)sLo * DOUT + col + 1, acc[mi][ni][1] + bb1);
                atomicAdd(out + (size_t)sHi * DOUT + col,     acc[mi][ni][2] + bb0);
                atomicAdd(out + (size_t)sHi * DOUT + col + 1, acc[mi][ni][3] + bb1);
            }
        }
    }
}

// ---------------------------------------------------------------------------
// prep: gather(optional) + rna-round + transpose into [panel][K][128]
// ---------------------------------------------------------------------------
__device__ __forceinline__ void prep_body(
    const float* __restrict__ src, float* __restrict__ dst,
    const int* __restrict__ gidx, int C)
{
    __shared__ float t[128][33];
    const int tid = threadIdx.x;
    const int c0 = blockIdx.x * 32;
    const int m0 = blockIdx.y * 128;

    #pragma unroll
    for (int i = 0; i < 4; i++) {
        int c = tid + i * 256, r = c >> 3, q = c & 7;
        int row = gidx ? __ldg(gidx + m0 + r) : (m0 + r);
        float4 v = *reinterpret_cast<const float4*>(src + (size_t)row * C + c0 + q * 4);
        t[r][q * 4 + 0] = __uint_as_float(f2tf32(v.x));
        t[r][q * 4 + 1] = __uint_as_float(f2tf32(v.y));
        t[r][q * 4 + 2] = __uint_as_float(f2tf32(v.z));
        t[r][q * 4 + 3] = __uint_as_float(f2tf32(v.w));
    }
    __syncthreads();
    float* dp = dst + (size_t)blockIdx.y * C * 128 + (size_t)c0 * 128;
    #pragma unroll
    for (int i = 0; i < 16; i++) {
        int e = tid + i * 256, k = e >> 7, rr = e & 127;
        dp[(size_t)k * 128 + rr] = t[rr][k];
    }
}

__global__ void prepX_kernel(const float* __restrict__ hidden, const int* __restrict__ gidx) {
    prep_body(hidden, g_Xp, gidx, H_DIM);
}
__global__ void prepW1_kernel(const float* __restrict__ W1) {
    prep_body(W1, g_W1p, nullptr, H_DIM);
}
__global__ void prepW2_kernel(const float* __restrict__ W2) {
    prep_body(W2, g_W2p, nullptr, DMID);
}
__global__ void zero_kernel(float* p, int n) {
    int i = blockIdx.x * blockDim.x + threadIdx.x;
    if (i < n) p[i] = 0.0f;
}

extern "C" void kernel_launch(void* const* d_in, const int* in_sizes, int n_in,
                              void* d_out, int out_size) {
    const float* hidden   = (const float*)d_in[0];
    const float* W1       = (const float*)d_in[1];
    const float* b1       = (const float*)d_in[2];
    const float* W2       = (const float*)d_in[3];
    const float* b2       = (const float*)d_in[4];
    const int*   flat_idx = (const int*)d_in[5];
    const int*   seg_ids  = (const int*)d_in[6];
    float* out = (float*)d_out;

    static bool attr_done = false;
    if (!attr_done) {
        cudaFuncSetAttribute(gemm1_kernel, cudaFuncAttributeMaxDynamicSharedMemorySize, SMEM_GEMM);
        cudaFuncSetAttribute(gemm2_kernel, cudaFuncAttributeMaxDynamicSharedMemorySize, SMEM_GEMM);
        attr_done = true;
    }

    zero_kernel<<<(out_size + 255) / 256, 256>>>(out, out_size);

    prepW1_kernel<<<dim3(H_DIM / 32, DMID / 128), NT>>>(W1);
    prepW2_kernel<<<dim3(DMID / 32,  DOUT / 128), NT>>>(W2);
    prepX_kernel <<<dim3(H_DIM / 32, M_TOK / 128), NT>>>(hidden, flat_idx);

    gemm1_kernel<<<dim3(DMID / BN, M_TOK / BM), NT, SMEM_GEMM>>>(b1);
    gemm2_kernel<<<dim3(DOUT / BN, M_TOK / BM), NT, SMEM_GEMM>>>(b2, seg_ids, out);
}

// round 12
// speedup vs baseline: 2.4761x; 1.0043x over previous
#include <cuda_runtime.h>
#include <cstdint>

#define M_TOK 32768
#define H_DIM 2048
#define DMID  1024
#define DOUT  256

#define BM 256
#define BN 128
#define BK 32
#define NT 256
#define KSTRIDE_W 136
#define TILE_B (BK * KSTRIDE_W * 4)      // 17408 per 32x128 tile
#define BUF_B  (3 * TILE_B)              // A0 A1 B = 52224
#define SMEM_GEMM (2 * BUF_B)            // 104448

__device__ float g_Xp [(size_t)M_TOK * H_DIM];   // [256 panels][2048][128]
__device__ float g_W1p[(size_t)DMID  * H_DIM];   // [8 panels][2048][128]
__device__ float g_W2p[(size_t)DOUT  * DMID];    // [2 panels][1024][128]
__device__ float g_h  [(size_t)M_TOK * DMID];    // [256 panels][1024][128]

__device__ __forceinline__ uint32_t smem_u32(const void* p) {
    uint32_t a;
    asm("{ .reg .u64 t; cvta.to.shared.u64 t, %1; cvt.u32.u64 %0, t; }" : "=r"(a) : "l"(p));
    return a;
}
__device__ __forceinline__ unsigned f2tf32(float x) {
    unsigned u; asm("cvt.rna.tf32.f32 %0, %1;" : "=r"(u) : "f"(x)); return u;
}
__device__ __forceinline__ void cp16(uint32_t dst, const float* src) {
    asm volatile("cp.async.cg.shared.global [%0], [%1], 16;"
                 :: "r"(dst), "l"(__cvta_generic_to_global(src)) : "memory");
}
#define CP_COMMIT() asm volatile("cp.async.commit_group;" ::: "memory")
#define CP_WAIT1()  asm volatile("cp.async.wait_group 1;" ::: "memory")
#define CP_WAIT0()  asm volatile("cp.async.wait_group 0;" ::: "memory")
#define LDSW(v, a)  asm volatile("ld.shared.b32 %0, [%1];" : "=r"(v) : "r"(a))

__device__ __forceinline__ void mma8(float c[4], const unsigned a[4], const unsigned b[2]) {
    asm volatile(
        "mma.sync.aligned.m16n8k8.row.col.f32.tf32.tf32.f32 "
        "{%0,%1,%2,%3}, {%4,%5,%6,%7}, {%8,%9}, {%0,%1,%2,%3};\n"
        : "+f"(c[0]), "+f"(c[1]), "+f"(c[2]), "+f"(c[3])
        : "r"(a[0]), "r"(a[1]), "r"(a[2]), "r"(a[3]), "r"(b[0]), "r"(b[1]));
}
__device__ __forceinline__ float mish_f(float x) {
    float t = __expf(x);
    float n = t * t + 2.0f * t;
    float r = x * __fdividef(n, n + 2.0f);
    return (x > 15.0f) ? x : r;
}

// ---------------------------------------------------------------------------
// Mainloop (round-5 pipeline, two A panel-tiles + one B tile per buffer).
// A0,A1,B: panel [K][128] sources. Warp tile 64x64.
// ---------------------------------------------------------------------------
__device__ __forceinline__ void gemm_mainloop(
    const float* __restrict__ A0, const float* __restrict__ A1,
    const float* __restrict__ B, int K, uint32_t sbase, float acc[4][8][4])
{
    const int tid = threadIdx.x;
    const int lane = tid & 31, warp = tid >> 5;
    const int warpM = warp >> 1, warpN = warp & 1;
    const int g = lane >> 2, tg = lane & 3;

    uint32_t buf[2] = { sbase, sbase + BUF_B };

    uint32_t doff[4]; int soff[4];
    #pragma unroll
    for (int i = 0; i < 4; i++) {
        int c = tid + i * 256, kk = c >> 5, mq = c & 31;
        doff[i] = (uint32_t)(kk * (KSTRIDE_W * 4) + mq * 16);
        soff[i] = kk * 128 + mq * 4;
    }

    #pragma unroll
    for (int i = 0; i < 4; i++) {
        cp16(buf[0] + doff[i],              A0 + soff[i]);
        cp16(buf[0] + TILE_B + doff[i],     A1 + soff[i]);
        cp16(buf[0] + 2 * TILE_B + doff[i], B  + soff[i]);
    }
    CP_COMMIT();

    const int S = K / BK;
    for (int s = 0; s < S; s++) {
        const int p = s & 1;
        if (s + 1 < S) {
            const int o1 = (s + 1) * (BK * 128);
            const int q = p ^ 1;
            #pragma unroll
            for (int i = 0; i < 4; i++) {
                cp16(buf[q] + doff[i],              A0 + o1 + soff[i]);
                cp16(buf[q] + TILE_B + doff[i],     A1 + o1 + soff[i]);
                cp16(buf[q] + 2 * TILE_B + doff[i], B  + o1 + soff[i]);
            }
            CP_COMMIT();
            CP_WAIT1();
        } else {
            CP_WAIT0();
        }
        __syncthreads();

        const uint32_t aB = buf[p] + (uint32_t)((warpM >> 1) * TILE_B)
                          + (uint32_t)(((warpM & 1) * 64) * 4);
        const uint32_t bB = buf[p] + 2 * TILE_B + (uint32_t)((warpN * 64) * 4);
        #pragma unroll
        for (int ks = 0; ks < BK; ks += 8) {
            unsigned a[4][4], b[8][2];
            const uint32_t rowLo = (uint32_t)((ks + tg) * (KSTRIDE_W * 4));
            const uint32_t rowHi = rowLo + 4 * (KSTRIDE_W * 4);
            #pragma unroll
            for (int mi = 0; mi < 4; mi++) {
                uint32_t o = (uint32_t)((mi * 16 + g) * 4);
                LDSW(a[mi][0], aB + rowLo + o);
                LDSW(a[mi][1], aB + rowLo + o + 32);
                LDSW(a[mi][2], aB + rowHi + o);
                LDSW(a[mi][3], aB + rowHi + o + 32);
            }
            #pragma unroll
            for (int ni = 0; ni < 8; ni++) {
                uint32_t o = (uint32_t)((ni * 8 + g) * 4);
                LDSW(b[ni][0], bB + rowLo + o);
                LDSW(b[ni][1], bB + rowHi + o);
            }
            #pragma unroll
            for (int mi = 0; mi < 4; mi++)
                #pragma unroll
                for (int ni = 0; ni < 8; ni++)
                    mma8(acc[mi][ni], a[mi], b[ni]);
        }
        __syncthreads();
    }
}

// -------- GEMM1: g_h[panel] = mish( Xp @ W1p^T + b1 ), tf32-rounded --------
__global__ __launch_bounds__(NT, 1) void gemm1_kernel(const float* __restrict__ b1)
{
    extern __shared__ char smem[];
    float acc[4][8][4];
    #pragma unroll
    for (int mi = 0; mi < 4; mi++)
        #pragma unroll
        for (int ni = 0; ni < 8; ni++)
            #pragma unroll
            for (int j = 0; j < 4; j++) acc[mi][ni][j] = 0.f;

    const int pan0 = blockIdx.y * 2;
    const float* A0 = g_Xp  + (size_t)pan0 * ((size_t)H_DIM * 128);
    const float* A1 = A0 + (size_t)H_DIM * 128;
    const float* Bp = g_W1p + (size_t)blockIdx.x * ((size_t)H_DIM * 128);
    gemm_mainloop(A0, A1, Bp, H_DIM, smem_u32(smem), acc);

    const int tid = threadIdx.x, lane = tid & 31, warp = tid >> 5;
    const int warpM = warp >> 1, warpN = warp & 1;
    const int g = lane >> 2, tg = lane & 3;
    const int n0 = blockIdx.x * BN;

    float* hp = g_h + (size_t)(pan0 + (warpM >> 1)) * ((size_t)DMID * 128);
    const int half = (warpM & 1) * 64;

    #pragma unroll
    for (int ni = 0; ni < 8; ni++) {
        int col = n0 + warpN * 64 + ni * 8 + 2 * tg;
        float bb0 = __ldg(b1 + col), bb1 = __ldg(b1 + col + 1);
        #pragma unroll
        for (int mi = 0; mi < 4; mi++) {
            int rl = half + mi * 16 + g;
            float* p0 = hp + (size_t)col * 128 + rl;
            p0[0]        = __uint_as_float(f2tf32(mish_f(acc[mi][ni][0] + bb0)));
            p0[128]      = __uint_as_float(f2tf32(mish_f(acc[mi][ni][1] + bb1)));
            p0[8]        = __uint_as_float(f2tf32(mish_f(acc[mi][ni][2] + bb0)));
            p0[128 + 8]  = __uint_as_float(f2tf32(mish_f(acc[mi][ni][3] + bb1)));
        }
    }
}

// -------- GEMM2: out[seg] += g_h @ W2p^T + b2 --------
__global__ __launch_bounds__(NT, 1) void gemm2_kernel(
    const float* __restrict__ b2, const int* __restrict__ seg_ids,
    float* __restrict__ out)
{
    extern __shared__ char smem[];
    float acc[4][8][4];
    #pragma unroll
    for (int mi = 0; mi < 4; mi++)
        #pragma unroll
        for (int ni = 0; ni < 8; ni++)
            #pragma unroll
            for (int j = 0; j < 4; j++) acc[mi][ni][j] = 0.f;

    const int pan0 = blockIdx.y * 2;
    const float* A0 = g_h + (size_t)pan0 * ((size_t)DMID * 128);
    const float* A1 = A0 + (size_t)DMID * 128;
    const float* Bp = g_W2p + (size_t)blockIdx.x * ((size_t)DMID * 128);
    gemm_mainloop(A0, A1, Bp, DMID, smem_u32(smem), acc);

    const int tid = threadIdx.x, lane = tid & 31, warp = tid >> 5;
    const int warpM = warp >> 1, warpN = warp & 1;
    const int g = lane >> 2, tg = lane & 3;
    const int m0 = blockIdx.y * BM;
    const int n0 = blockIdx.x * BN;
    const int rbase = (warpM >> 1) * 128 + (warpM & 1) * 64;

    const int segF = __ldg(seg_ids + m0);
    const int segL = __ldg(seg_ids + m0 + BM - 1);

    if (segF == segL) {
        float* orow = out + (size_t)segF * DOUT;
        #pragma unroll
        for (int ni = 0; ni < 8; ni++) {
            float v0 = 0.f, v1 = 0.f;
            #pragma unroll
            for (int mi = 0; mi < 4; mi++) {
                v0 += acc[mi][ni][0] + acc[mi][ni][2];
                v1 += acc[mi][ni][1] + acc[mi][ni][3];
            }
            #pragma unroll
            for (int m = 4; m <= 16; m <<= 1) {
                v0 += __shfl_xor_sync(0xffffffffu, v0, m);
                v1 += __shfl_xor_sync(0xffffffffu, v1, m);
            }
            if (lane < 4) {
                int col = n0 + warpN * 64 + ni * 8 + 2 * lane;
                atomicAdd(orow + col,     v0 + 64.0f * __ldg(b2 + col));
                atomicAdd(orow + col + 1, v1 + 64.0f * __ldg(b2 + col + 1));
            }
        }
    } else {
        #pragma unroll
        for (int mi = 0; mi < 4; mi++) {
            int R = m0 + rbase + mi * 16 + g;
            int sLo = __ldg(seg_ids + R), sHi = __ldg(seg_ids + R + 8);
            #pragma unroll
            for (int ni = 0; ni < 8; ni++) {
                int col = n0 + warpN * 64 + ni * 8 + 2 * tg;
                float bb0 = __ldg(b2 + col), bb1 = __ldg(b2 + col + 1);
                atomicAdd(out + (size_t)sLo * DOUT + col,     acc[mi][ni][0] + bb0);
                atomicAdd(out + (size_t)sLo * DOUT + col + 1, acc[mi][ni][1] + bb1);
                atomicAdd(out + (size_t)sHi * DOUT + col,     acc[mi][ni][2] + bb0);
                atomicAdd(out + (size_t)sHi * DOUT + col + 1, acc[mi][ni][3] + bb1);
            }
        }
    }
}

// ---------------------------------------------------------------------------
// prep: identical to round 5 (passing)
// ---------------------------------------------------------------------------
__device__ __forceinline__ void prep_body(
    const float* __restrict__ src, float* __restrict__ dst,
    const int* __restrict__ gidx, int C)
{
    __shared__ float t[128][33];
    const int tid = threadIdx.x;
    const int c0 = blockIdx.x * 32;
    const int m0 = blockIdx.y * 128;

    #pragma unroll
    for (int i = 0; i < 4; i++) {
        int c = tid + i * 256, r = c >> 3, q = c & 7;
        int row = gidx ? __ldg(gidx + m0 + r) : (m0 + r);
        float4 v = *reinterpret_cast<const float4*>(src + (size_t)row * C + c0 + q * 4);
        t[r][q * 4 + 0] = __uint_as_float(f2tf32(v.x));
        t[r][q * 4 + 1] = __uint_as_float(f2tf32(v.y));
        t[r][q * 4 + 2] = __uint_as_float(f2tf32(v.z));
        t[r][q * 4 + 3] = __uint_as_float(f2tf32(v.w));
    }
    __syncthreads();
    float* dp = dst + (size_t)blockIdx.y * C * 128 + (size_t)c0 * 128;
    #pragma unroll
    for (int i = 0; i < 16; i++) {
        int e = tid + i * 256, k = e >> 7, rr = e & 127;
        dp[(size_t)k * 128 + rr] = t[rr][k];
    }
}

__global__ void prepX_kernel(const float* __restrict__ hidden, const int* __restrict__ gidx) {
    prep_body(hidden, g_Xp, gidx, H_DIM);
}
__global__ void prepW1_kernel(const float* __restrict__ W1) {
    prep_body(W1, g_W1p, nullptr, H_DIM);
}
__global__ void prepW2_kernel(const float* __restrict__ W2) {
    prep_body(W2, g_W2p, nullptr, DMID);
}
__global__ void zero_kernel(float* p, int n) {
    int i = blockIdx.x * blockDim.x + threadIdx.x;
    if (i < n) p[i] = 0.0f;
}

extern "C" void kernel_launch(void* const* d_in, const int* in_sizes, int n_in,
                              void* d_out, int out_size) {
    const float* hidden   = (const float*)d_in[0];
    const float* W1       = (const float*)d_in[1];
    const float* b1       = (const float*)d_in[2];
    const float* W2       = (const float*)d_in[3];
    const float* b2       = (const float*)d_in[4];
    const int*   flat_idx = (const int*)d_in[5];
    const int*   seg_ids  = (const int*)d_in[6];
    float* out = (float*)d_out;

    cudaFuncSetAttribute(gemm1_kernel, cudaFuncAttributeMaxDynamicSharedMemorySize, SMEM_GEMM);
    cudaFuncSetAttribute(gemm2_kernel, cudaFuncAttributeMaxDynamicSharedMemorySize, SMEM_GEMM);

    zero_kernel<<<(out_size + 255) / 256, 256>>>(out, out_size);

    prepW1_kernel<<<dim3(H_DIM / 32, DMID / 128), NT>>>(W1);
    prepW2_kernel<<<dim3(DMID / 32,  DOUT / 128), NT>>>(W2);
    prepX_kernel <<<dim3(H_DIM / 32, M_TOK / 128), NT>>>(hidden, flat_idx);

    gemm1_kernel<<<dim3(DMID / BN, M_TOK / BM), NT, SMEM_GEMM>>>(b1);              // (8,128)
    gemm2_kernel<<<dim3(DOUT / BN, M_TOK / BM), NT, SMEM_GEMM>>>(b2, seg_ids, out); // (2,128)
}

// round 13
// speedup vs baseline: 4.5416x; 1.8342x over previous
#include <cuda_runtime.h>
#include <cuda_fp16.h>
#include <cstdint>

#define M_TOK 32768
#define H_DIM 2048
#define DMID  1024
#define DOUT  256

#define BM 256
#define BN 128
#define BKE 64                            // k-elements per stage (32 word-rows)
#define NT 256
#define KSTRIDE_W 136
#define TILE_B (32 * KSTRIDE_W * 4)       // 17408 per 32-wordrow x 128 tile
#define BUF_B  (3 * TILE_B)
#define SMEM_GEMM (2 * BUF_B)             // 104448

// packed fp16-pair panels: word(k2, m) = {h(2k2,m), h(2k2+1,m)}
__device__ uint32_t g_Xp [(size_t)M_TOK * H_DIM / 2];   // [256 pan][1024][128]
__device__ uint32_t g_W1p[(size_t)DMID  * H_DIM / 2];   // [8 pan][1024][128]
__device__ uint32_t g_W2p[(size_t)DOUT  * DMID / 2];    // [2 pan][512][128]
__device__ uint32_t g_h  [(size_t)M_TOK * DMID / 2];    // [256 pan][512][128]

__device__ __forceinline__ uint32_t smem_u32(const void* p) {
    uint32_t a;
    asm("{ .reg .u64 t; cvta.to.shared.u64 t, %1; cvt.u32.u64 %0, t; }" : "=r"(a) : "l"(p));
    return a;
}
__device__ __forceinline__ uint32_t pack_h2(float x, float y) {
    __half2 h = __floats2half2_rn(x, y);
    return *reinterpret_cast<uint32_t*>(&h);
}
__device__ __forceinline__ void cp16(uint32_t dst, const uint32_t* src) {
    asm volatile("cp.async.cg.shared.global [%0], [%1], 16;"
                 :: "r"(dst), "l"(__cvta_generic_to_global(src)) : "memory");
}
#define CP_COMMIT() asm volatile("cp.async.commit_group;" ::: "memory")
#define CP_WAIT1()  asm volatile("cp.async.wait_group 1;" ::: "memory")
#define CP_WAIT0()  asm volatile("cp.async.wait_group 0;" ::: "memory")
#define LDSW(v, a)  asm volatile("ld.shared.b32 %0, [%1];" : "=r"(v) : "r"(a))

__device__ __forceinline__ void mma16(float c[4], const unsigned a[4], const unsigned b[2]) {
    asm volatile(
        "mma.sync.aligned.m16n8k16.row.col.f32.f16.f16.f32 "
        "{%0,%1,%2,%3}, {%4,%5,%6,%7}, {%8,%9}, {%0,%1,%2,%3};\n"
        : "+f"(c[0]), "+f"(c[1]), "+f"(c[2]), "+f"(c[3])
        : "r"(a[0]), "r"(a[1]), "r"(a[2]), "r"(a[3]), "r"(b[0]), "r"(b[1]));
}
__device__ __forceinline__ float mish_f(float x) {
    float t = __expf(x);
    float n = t * t + 2.0f * t;
    float r = x * __fdividef(n, n + 2.0f);
    return (x > 15.0f) ? x : r;
}

// ---------------------------------------------------------------------------
// Mainloop: identical addressing to the proven tf32 version; word-rows are
// k-pairs, each inner ks-step covers 16 k-elements via m16n8k16.
// ---------------------------------------------------------------------------
__device__ __forceinline__ void gemm_mainloop(
    const uint32_t* __restrict__ A0, const uint32_t* __restrict__ A1,
    const uint32_t* __restrict__ B, int K, uint32_t sbase, float acc[4][8][4])
{
    const int tid = threadIdx.x;
    const int lane = tid & 31, warp = tid >> 5;
    const int warpM = warp >> 1, warpN = warp & 1;
    const int g = lane >> 2, tg = lane & 3;

    uint32_t buf[2] = { sbase, sbase + BUF_B };

    uint32_t doff[4]; int soff[4];
    #pragma unroll
    for (int i = 0; i < 4; i++) {
        int c = tid + i * 256, kk = c >> 5, mq = c & 31;
        doff[i] = (uint32_t)(kk * (KSTRIDE_W * 4) + mq * 16);
        soff[i] = kk * 128 + mq * 4;
    }

    #pragma unroll
    for (int i = 0; i < 4; i++) {
        cp16(buf[0] + doff[i],              A0 + soff[i]);
        cp16(buf[0] + TILE_B + doff[i],     A1 + soff[i]);
        cp16(buf[0] + 2 * TILE_B + doff[i], B  + soff[i]);
    }
    CP_COMMIT();

    const int S = K / BKE;
    for (int s = 0; s < S; s++) {
        const int p = s & 1;
        if (s + 1 < S) {
            const int o1 = (s + 1) * (32 * 128);
            const int q = p ^ 1;
            #pragma unroll
            for (int i = 0; i < 4; i++) {
                cp16(buf[q] + doff[i],              A0 + o1 + soff[i]);
                cp16(buf[q] + TILE_B + doff[i],     A1 + o1 + soff[i]);
                cp16(buf[q] + 2 * TILE_B + doff[i], B  + o1 + soff[i]);
            }
            CP_COMMIT();
            CP_WAIT1();
        } else {
            CP_WAIT0();
        }
        __syncthreads();

        const uint32_t aB = buf[p] + (uint32_t)((warpM >> 1) * TILE_B)
                          + (uint32_t)(((warpM & 1) * 64) * 4);
        const uint32_t bB = buf[p] + 2 * TILE_B + (uint32_t)((warpN * 64) * 4);
        #pragma unroll
        for (int ks = 0; ks < 32; ks += 8) {
            unsigned a[4][4], b[8][2];
            const uint32_t rowLo = (uint32_t)((ks + tg) * (KSTRIDE_W * 4));
            const uint32_t rowHi = rowLo + 4 * (KSTRIDE_W * 4);
            #pragma unroll
            for (int mi = 0; mi < 4; mi++) {
                uint32_t o = (uint32_t)((mi * 16 + g) * 4);
                LDSW(a[mi][0], aB + rowLo + o);
                LDSW(a[mi][1], aB + rowLo + o + 32);
                LDSW(a[mi][2], aB + rowHi + o);
                LDSW(a[mi][3], aB + rowHi + o + 32);
            }
            #pragma unroll
            for (int ni = 0; ni < 8; ni++) {
                uint32_t o = (uint32_t)((ni * 8 + g) * 4);
                LDSW(b[ni][0], bB + rowLo + o);
                LDSW(b[ni][1], bB + rowHi + o);
            }
            #pragma unroll
            for (int mi = 0; mi < 4; mi++)
                #pragma unroll
                for (int ni = 0; ni < 8; ni++)
                    mma16(acc[mi][ni], a[mi], b[ni]);
        }
        __syncthreads();
    }
}

// -------- GEMM1: g_h[panel] = mish( Xp @ W1p^T + b1 ) as packed fp16 -------
__global__ __launch_bounds__(NT, 1) void gemm1_kernel(const float* __restrict__ b1)
{
    extern __shared__ char smem[];
    float acc[4][8][4];
    #pragma unroll
    for (int mi = 0; mi < 4; mi++)
        #pragma unroll
        for (int ni = 0; ni < 8; ni++)
            #pragma unroll
            for (int j = 0; j < 4; j++) acc[mi][ni][j] = 0.f;

    const int pan0 = blockIdx.y * 2;
    const uint32_t* A0 = g_Xp  + (size_t)pan0 * ((size_t)H_DIM * 64);
    const uint32_t* A1 = A0 + (size_t)H_DIM * 64;
    const uint32_t* Bp = g_W1p + (size_t)blockIdx.x * ((size_t)H_DIM * 64);
    gemm_mainloop(A0, A1, Bp, H_DIM, smem_u32(smem), acc);

    const int tid = threadIdx.x, lane = tid & 31, warp = tid >> 5;
    const int warpM = warp >> 1, warpN = warp & 1;
    const int g = lane >> 2, tg = lane & 3;
    const int n0 = blockIdx.x * BN;

    uint32_t* hp = g_h + (size_t)(pan0 + (warpM >> 1)) * ((size_t)DMID * 64);
    const int half = (warpM & 1) * 64;

    #pragma unroll
    for (int ni = 0; ni < 8; ni++) {
        int col = n0 + warpN * 64 + ni * 8 + 2 * tg;
        float bb0 = __ldg(b1 + col), bb1 = __ldg(b1 + col + 1);
        uint32_t* cp = hp + (size_t)(col >> 1) * 128;
        #pragma unroll
        for (int mi = 0; mi < 4; mi++) {
            int rl = half + mi * 16 + g;
            cp[rl]     = pack_h2(mish_f(acc[mi][ni][0] + bb0), mish_f(acc[mi][ni][1] + bb1));
            cp[rl + 8] = pack_h2(mish_f(acc[mi][ni][2] + bb0), mish_f(acc[mi][ni][3] + bb1));
        }
    }
}

// -------- GEMM2: out[seg] += g_h @ W2p^T + b2 --------
__global__ __launch_bounds__(NT, 1) void gemm2_kernel(
    const float* __restrict__ b2, const int* __restrict__ seg_ids,
    float* __restrict__ out)
{
    extern __shared__ char smem[];
    float acc[4][8][4];
    #pragma unroll
    for (int mi = 0; mi < 4; mi++)
        #pragma unroll
        for (int ni = 0; ni < 8; ni++)
            #pragma unroll
            for (int j = 0; j < 4; j++) acc[mi][ni][j] = 0.f;

    const int pan0 = blockIdx.y * 2;
    const uint32_t* A0 = g_h + (size_t)pan0 * ((size_t)DMID * 64);
    const uint32_t* A1 = A0 + (size_t)DMID * 64;
    const uint32_t* Bp = g_W2p + (size_t)blockIdx.x * ((size_t)DMID * 64);
    gemm_mainloop(A0, A1, Bp, DMID, smem_u32(smem), acc);

    const int tid = threadIdx.x, lane = tid & 31, warp = tid >> 5;
    const int warpM = warp >> 1, warpN = warp & 1;
    const int g = lane >> 2, tg = lane & 3;
    const int m0 = blockIdx.y * BM;
    const int n0 = blockIdx.x * BN;
    const int rbase = (warpM >> 1) * 128 + (warpM & 1) * 64;

    const int segF = __ldg(seg_ids + m0);
    const int segL = __ldg(seg_ids + m0 + BM - 1);

    if (segF == segL) {
        float* orow = out + (size_t)segF * DOUT;
        #pragma unroll
        for (int ni = 0; ni < 8; ni++) {
            float v0 = 0.f, v1 = 0.f;
            #pragma unroll
            for (int mi = 0; mi < 4; mi++) {
                v0 += acc[mi][ni][0] + acc[mi][ni][2];
                v1 += acc[mi][ni][1] + acc[mi][ni][3];
            }
            #pragma unroll
            for (int m = 4; m <= 16; m <<= 1) {
                v0 += __shfl_xor_sync(0xffffffffu, v0, m);
                v1 += __shfl_xor_sync(0xffffffffu, v1, m);
            }
            if (lane < 4) {
                int col = n0 + warpN * 64 + ni * 8 + 2 * lane;
                atomicAdd(orow + col,     v0 + 64.0f * __ldg(b2 + col));
                atomicAdd(orow + col + 1, v1 + 64.0f * __ldg(b2 + col + 1));
            }
        }
    } else {
        #pragma unroll
        for (int mi = 0; mi < 4; mi++) {
            int R = m0 + rbase + mi * 16 + g;
            int sLo = __ldg(seg_ids + R), sHi = __ldg(seg_ids + R + 8);
            #pragma unroll
            for (int ni = 0; ni < 8; ni++) {
                int col = n0 + warpN * 64 + ni * 8 + 2 * tg;
                float bb0 = __ldg(b2 + col), bb1 = __ldg(b2 + col + 1);
                atomicAdd(out + (size_t)sLo * DOUT + col,     acc[mi][ni][0] + bb0);
                atomicAdd(out + (size_t)sLo * DOUT + col + 1, acc[mi][ni][1] + bb1);
                atomicAdd(out + (size_t)sHi * DOUT + col,     acc[mi][ni][2] + bb0);
                atomicAdd(out + (size_t)sHi * DOUT + col + 1, acc[mi][ni][3] + bb1);
            }
        }
    }
}

// ---------------------------------------------------------------------------
// prep: gather(optional) + transpose + fp16-pair pack into [pan][C/2][128]
// ---------------------------------------------------------------------------
__device__ __forceinline__ void prep_body(
    const float* __restrict__ src, uint32_t* __restrict__ dst,
    const int* __restrict__ gidx, int C)
{
    __shared__ float t[128][33];
    const int tid = threadIdx.x;
    const int c0 = blockIdx.x * 32;
    const int m0 = blockIdx.y * 128;

    #pragma unroll
    for (int i = 0; i < 4; i++) {
        int c = tid + i * 256, r = c >> 3, q = c & 7;
        int row = gidx ? __ldg(gidx + m0 + r) : (m0 + r);
        float4 v = *reinterpret_cast<const float4*>(src + (size_t)row * C + c0 + q * 4);
        t[r][q * 4 + 0] = v.x;
        t[r][q * 4 + 1] = v.y;
        t[r][q * 4 + 2] = v.z;
        t[r][q * 4 + 3] = v.w;
    }
    __syncthreads();
    uint32_t* dp = dst + (size_t)blockIdx.y * ((size_t)(C >> 1) * 128)
                 + (size_t)(c0 >> 1) * 128;
    #pragma unroll
    for (int i = 0; i < 8; i++) {
        int e = tid + i * 256, k2 = e >> 7, rr = e & 127;
        dp[(size_t)k2 * 128 + rr] = pack_h2(t[rr][2 * k2], t[rr][2 * k2 + 1]);
    }
}

__global__ void prepX_kernel(const float* __restrict__ hidden, const int* __restrict__ gidx) {
    prep_body(hidden, g_Xp, gidx, H_DIM);
}
__global__ void prepW1_kernel(const float* __restrict__ W1) {
    prep_body(W1, g_W1p, nullptr, H_DIM);
}
__global__ void prepW2_kernel(const float* __restrict__ W2) {
    prep_body(W2, g_W2p, nullptr, DMID);
}
__global__ void zero_kernel(float* p, int n) {
    int i = blockIdx.x * blockDim.x + threadIdx.x;
    if (i < n) p[i] = 0.0f;
}

extern "C" void kernel_launch(void* const* d_in, const int* in_sizes, int n_in,
                              void* d_out, int out_size) {
    const float* hidden   = (const float*)d_in[0];
    const float* W1       = (const float*)d_in[1];
    const float* b1       = (const float*)d_in[2];
    const float* W2       = (const float*)d_in[3];
    const float* b2       = (const float*)d_in[4];
    const int*   flat_idx = (const int*)d_in[5];
    const int*   seg_ids  = (const int*)d_in[6];
    float* out = (float*)d_out;

    cudaFuncSetAttribute(gemm1_kernel, cudaFuncAttributeMaxDynamicSharedMemorySize, SMEM_GEMM);
    cudaFuncSetAttribute(gemm2_kernel, cudaFuncAttributeMaxDynamicSharedMemorySize, SMEM_GEMM);

    zero_kernel<<<(out_size + 255) / 256, 256>>>(out, out_size);

    prepW1_kernel<<<dim3(H_DIM / 32, DMID / 128), NT>>>(W1);
    prepW2_kernel<<<dim3(DMID / 32,  DOUT / 128), NT>>>(W2);
    prepX_kernel <<<dim3(H_DIM / 32, M_TOK / 128), NT>>>(hidden, flat_idx);

    gemm1_kernel<<<dim3(DMID / BN, M_TOK / BM), NT, SMEM_GEMM>>>(b1);               // (8,128)
    gemm2_kernel<<<dim3(DOUT / BN, M_TOK / BM), NT, SMEM_GEMM>>>(b2, seg_ids, out);  // (2,128)
}